// round 15
// baseline (speedup 1.0000x reference)
#include <cuda_runtime.h>
#include <math.h>

#define N_LEVELS      16
#define HASHMAP_SIZE  (1u << 19)
#define HASH_MASK     (HASHMAP_SIZE - 1u)
#define P2            2654435761u
#define P3            805459861u

struct ResTable {
    int res[N_LEVELS];
};

// 8 lanes per point (one corner each), 4 points per warp.  R14 skeleton with
// depth-1 software pipelining: level l+1's gather is issued before level l's
// data is consumed, keeping one gather in flight across every level boundary.
__global__ void __launch_bounds__(256)
hashenc_kernel(const float* __restrict__ pos,
               const float* __restrict__ emb,
               float* __restrict__ out,
               ResTable rt,
               int n_points)
{
    const int tid  = blockIdx.x * blockDim.x + threadIdx.x;
    const int lane = threadIdx.x & 31;
    const int c    = lane & 7;          // corner id: (i<<2)|(j<<1)|k
    const int sub  = lane >> 3;         // point slot within warp (0..3)
    const int p    = (tid >> 5) * 4 + sub;

    const bool valid = (p < n_points);
    const int  pp    = valid ? p : 0;

    const unsigned bi = (c >> 2) & 1;
    const unsigned bj = (c >> 1) & 1;
    const unsigned bk =  c       & 1;

    // weight via FMA: a = s*w + o  (s=+1,o=0 if corner bit set; s=-1,o=1 else)
    const float sxw = bi ? 1.f : -1.f, oxw = bi ? 0.f : 1.f;
    const float syw = bj ? 1.f : -1.f, oyw = bj ? 0.f : 1.f;
    const float szw = bk ? 1.f : -1.f, ozw = bk ? 0.f : 1.f;

    const float px = pos[pp * 3 + 0];
    const float py = pos[pp * 3 + 1];
    const float pz = pos[pp * 3 + 2];

    // ---- per-level index + weight + issue gather ----
    auto level_issue = [&](int l, float2*& addr_out, float& w_out) {
        const int   res  = rt.res[l];
        const float fres = (float)res;

        const float sx = px * fres, sy = py * fres, sz = pz * fres;
        const float fx = floorf(sx), fy = floorf(sy), fz = floorf(sz);
        const float wx = sx - fx,   wy = sy - fy,   wz = sz - fz;

        const unsigned ux = (unsigned)(int)fx + bi;
        const unsigned uy = (unsigned)(int)fy + bj;
        const unsigned uz = (unsigned)(int)fz + bk;

        const unsigned r1 = (unsigned)(res + 1);
        const bool dense =
            ((long long)r1 * (long long)r1 * (long long)r1) <= (long long)HASHMAP_SIZE;

        unsigned idx;
        if (dense) {
            idx = ux * (r1 * r1) + uy * r1 + uz;
        } else {
            idx = (ux ^ (uy * P2) ^ (uz * P3)) & HASH_MASK;
        }

        addr_out = const_cast<float2*>(
            reinterpret_cast<const float2*>(emb) + (size_t)l * HASHMAP_SIZE + idx);

        const float ax = fmaf(sxw, wx, oxw);
        const float ay = fmaf(syw, wy, oyw);
        const float az = fmaf(szw, wz, ozw);
        w_out = ax * ay * az;
    };

    auto do_load = [&](int l, const float2* a) -> float2 {
        return (l <= 1) ? __ldg(a) : __ldcg(a);
    };

    // lane c keeps results for levels 2c and 2c+1
    float acc0 = 0.f, acc1 = 0.f, acc2 = 0.f, acc3 = 0.f;

    // prologue: level 0
    float2* addr;  float wcur;
    level_issue(0, addr, wcur);
    float2 fcur = do_load(0, addr);

#pragma unroll
    for (int l = 0; l < N_LEVELS; ++l) {
        // issue next level's gather before consuming current data
        float2 fnext;  float wnext;
        if (l + 1 < N_LEVELS) {
            float2* anext;
            level_issue(l + 1, anext, wnext);
            fnext = do_load(l + 1, anext);
        }

        float v0 = fcur.x * wcur;
        float v1 = fcur.y * wcur;

        v0 += __shfl_xor_sync(0xffffffffu, v0, 4);
        v1 += __shfl_xor_sync(0xffffffffu, v1, 4);
        v0 += __shfl_xor_sync(0xffffffffu, v0, 2);
        v1 += __shfl_xor_sync(0xffffffffu, v1, 2);
        v0 += __shfl_xor_sync(0xffffffffu, v0, 1);
        v1 += __shfl_xor_sync(0xffffffffu, v1, 1);

        if ((l >> 1) == c) {
            if (l & 1) { acc2 = v0; acc3 = v1; }
            else       { acc0 = v0; acc1 = v1; }
        }

        if (l + 1 < N_LEVELS) { fcur = fnext; wcur = wnext; }
    }

    if (valid) {
        float4* __restrict__ o4 = reinterpret_cast<float4*>(out);
        o4[(size_t)p * 8 + c] = make_float4(acc0, acc1, acc2, acc3);
    }
}

extern "C" void kernel_launch(void* const* d_in, const int* in_sizes, int n_in,
                              void* d_out, int out_size)
{
    const float* positions  = (const float*)d_in[0];   // [N_POINTS, 3] f32
    const float* embeddings = (const float*)d_in[1];   // [16, 2^19, 2] f32
    float*       out        = (float*)d_out;           // [N_POINTS, 32] f32

    const int n_points = in_sizes[0] / 3;

    // Mirror numpy exactly in double precision (libm exp/log/pow)
    ResTable rt;
    const double scale = exp((log(2048.0) - log(16.0)) / 15.0);
    for (int l = 0; l < N_LEVELS; ++l) {
        rt.res[l] = (int)floor(16.0 * pow(scale, (double)l));
    }

    const long long total_threads = (long long)n_points * 8;
    const int threads = 256;
    const int blocks  = (int)((total_threads + threads - 1) / threads);
    hashenc_kernel<<<blocks, threads>>>(positions, embeddings, out, rt, n_points);
}